// round 5
// baseline (speedup 1.0000x reference)
#include <cuda_runtime.h>

#define N_NODES 8
#define B_      4
#define C_      32
#define HW      9216           // 96*96
#define P_      128            // pixels per block tile
#define NT      (HW / P_)      // 72
#define TOTAL   (N_NODES * B_ * C_ * HW)

// smem layout (floats)
#define XS_OFF  0                        // [8][32][128] = 32768
#define WD_OFF  32768                    // [8][32][36]  = 9216
#define WC_OFF  (WD_OFF + 9216)          // 9216
#define BS_OFF  (WC_OFF + 9216)          // 256
#define SMEM_FLOATS (BS_OFF + 256)
#define SMEM_BYTES  (SMEM_FLOATS * 4)    // 205,824 B

__device__ float g_buf0[TOTAL];
__device__ float g_buf1[TOTAL];

__device__ __forceinline__ unsigned long long fma_f32x2(
    unsigned long long a, unsigned long long b, unsigned long long c) {
    unsigned long long d;
    asm("fma.rn.f32x2 %0, %1, %2, %3;" : "=l"(d) : "l"(a), "l"(b), "l"(c));
    return d;
}
union U2 { unsigned long long u; float2 f; };
__device__ __forceinline__ unsigned long long pack2(float lo, float hi) {
    U2 t; t.f.x = lo; t.f.y = hi; return t.u;
}

// One GEMM mainloop: accY[m*4+p] (+)= {w[k][o0+2m], w[k][o0+2m+1]} * x[k][px+p]
// Also stashes x[k][px..px+3] into sx when k is in this warp's o-range.
#define GEMM_BODY(WB, XR)                                                     \
  _Pragma("unroll")                                                           \
  for (int k = 0; k < 32; ++k) {                                              \
      const ulonglong2 wA = *(const ulonglong2*)((WB) + k*36 + o0);           \
      const ulonglong2 wB = *(const ulonglong2*)((WB) + k*36 + o0 + 4);       \
      const float4 xv = *(const float4*)((XR) + k*P_ + px);                   \
      if ((k >> 3) == wg) {                                                   \
          sx[k & 7][0] = xv.x; sx[k & 7][1] = xv.y;                           \
          sx[k & 7][2] = xv.z; sx[k & 7][3] = xv.w;                           \
      }                                                                       \
      const unsigned long long x0 = pack2(xv.x, xv.x);                        \
      const unsigned long long x1 = pack2(xv.y, xv.y);                        \
      const unsigned long long x2 = pack2(xv.z, xv.z);                        \
      const unsigned long long x3 = pack2(xv.w, xv.w);                        \
      accY[0]  = fma_f32x2(wA.x, x0, accY[0]);                                \
      accY[1]  = fma_f32x2(wA.x, x1, accY[1]);                                \
      accY[2]  = fma_f32x2(wA.x, x2, accY[2]);                                \
      accY[3]  = fma_f32x2(wA.x, x3, accY[3]);                                \
      accY[4]  = fma_f32x2(wA.y, x0, accY[4]);                                \
      accY[5]  = fma_f32x2(wA.y, x1, accY[5]);                                \
      accY[6]  = fma_f32x2(wA.y, x2, accY[6]);                                \
      accY[7]  = fma_f32x2(wA.y, x3, accY[7]);                                \
      accY[8]  = fma_f32x2(wB.x, x0, accY[8]);                                \
      accY[9]  = fma_f32x2(wB.x, x1, accY[9]);                                \
      accY[10] = fma_f32x2(wB.x, x2, accY[10]);                               \
      accY[11] = fma_f32x2(wB.x, x3, accY[11]);                               \
      accY[12] = fma_f32x2(wB.y, x0, accY[12]);                               \
      accY[13] = fma_f32x2(wB.y, x1, accY[13]);                               \
      accY[14] = fma_f32x2(wB.y, x2, accY[14]);                               \
      accY[15] = fma_f32x2(wB.y, x3, accY[15]);                               \
  }

// out[i] = x_i + sum_{j!=i} relu(Wd_i @ x_j + C_i) * x_j,
// C_i = (Ws_i - Wd_i) @ x_i + b_i
extern "C" __global__ void __launch_bounds__(256, 1)
step_kernel(const float* __restrict__ in,
            const float* __restrict__ W_edge,   // [8][32][64]
            const float* __restrict__ b_edge,   // [8][32]
            float* __restrict__ out)
{
    extern __shared__ float sm[];
    float* xs   = sm + XS_OFF;   // [node][c][P_]
    float* wd_s = sm + WD_OFF;   // [i][d][36] (o fastest, padded)
    float* wc_s = sm + WC_OFF;
    float* bs   = sm + BS_OFF;

    const int bx    = blockIdx.x;
    const int b     = bx / NT;
    const int pbase = (bx % NT) * P_;
    const int tid   = threadIdx.x;

    // ---- x tile: 32768 floats = 8192 float4, 32 per thread, coalesced ----
    #pragma unroll
    for (int t = 0; t < 32; ++t) {
        const int e   = tid + t * 256;     // 0..8191
        const int row = e >> 5;            // node*32 + c
        const int c4  = e & 31;
        const int node = row >> 5, c = row & 31;
        const float4 v = *reinterpret_cast<const float4*>(
            in + ((node * B_ + b) * C_ + c) * HW + pbase + c4 * 4);
        *reinterpret_cast<float4*>(xs + row * P_ + c4 * 4) = v;
    }

    // ---- weights: transpose [i][o][d] -> [i][d][o] (stride-36 rows) ----
    // 8192 (i,o,d) triples, 256 threads -> 32 iterations (FIXED: was 64 = OOB)
    #pragma unroll
    for (int t = 0; t < 32; ++t) {
        const int e = tid + t * 256;       // 0..8191
        const int d = e & 31;
        const int o = (e >> 5) & 31;
        const int i = e >> 10;             // 0..7
        const float wd = W_edge[(i * C_ + o) * (2 * C_) + d];
        const float ws = W_edge[(i * C_ + o) * (2 * C_) + C_ + d];
        wd_s[(i * 32 + d) * 36 + o] = wd;
        wc_s[(i * 32 + d) * 36 + o] = ws - wd;
    }
    bs[tid] = b_edge[tid];                 // 256 = 8*32
    __syncthreads();

    const int h    = tid >> 7;             // half -> receiver parity
    const int wg   = (tid >> 5) & 3;       // o-group
    const int o0   = wg << 3;
    const int lane = tid & 31;
    const int px   = lane << 2;

    unsigned long long accY[16], accC[16];
    float accO[8][4];
    float sx[8][4];

    #pragma unroll 1
    for (int it = 0; it < 4; ++it) {
        const int i_n = (it << 1) + h;
        const float* wdi = wd_s + i_n * (32 * 36);
        const float* wci = wc_s + i_n * (32 * 36);

        // ---- C-GEMM: C = Wc_i @ x_i + b_i (also stashes x_i for residual) ----
        {
            const float* bsrc = bs + i_n * 32 + o0;
            #pragma unroll
            for (int m = 0; m < 4; ++m) {
                const unsigned long long bb = pack2(bsrc[2 * m], bsrc[2 * m + 1]);
                accY[m * 4 + 0] = bb; accY[m * 4 + 1] = bb;
                accY[m * 4 + 2] = bb; accY[m * 4 + 3] = bb;
            }
            const float* xrow = xs + i_n * (32 * P_);
            GEMM_BODY(wci, xrow)
            #pragma unroll
            for (int q = 0; q < 16; ++q) accC[q] = accY[q];
            #pragma unroll
            for (int n = 0; n < 8; ++n) {
                accO[n][0] = sx[n][0]; accO[n][1] = sx[n][1];
                accO[n][2] = sx[n][2]; accO[n][3] = sx[n][3];
            }
        }

        // ---- j-loop ----
        #pragma unroll 1
        for (int jl = 0; jl < 7; ++jl) {
            const int jj = jl + (jl >= i_n ? 1 : 0);
            #pragma unroll
            for (int q = 0; q < 16; ++q) accY[q] = accC[q];
            const float* xrow = xs + jj * (32 * P_);
            GEMM_BODY(wdi, xrow)
            // epilogue: out += relu(Y) * x_j  (sx holds x_j[o0..o0+7][px..px+3])
            #pragma unroll
            for (int m = 0; m < 4; ++m) {
                #pragma unroll
                for (int p = 0; p < 4; ++p) {
                    U2 y; y.u = accY[m * 4 + p];
                    const float g0 = fmaxf(y.f.x, 0.0f);
                    const float g1 = fmaxf(y.f.y, 0.0f);
                    accO[2 * m + 0][p] = fmaf(g0, sx[2 * m + 0][p], accO[2 * m + 0][p]);
                    accO[2 * m + 1][p] = fmaf(g1, sx[2 * m + 1][p], accO[2 * m + 1][p]);
                }
            }
        }

        // ---- store ----
        #pragma unroll
        for (int n = 0; n < 8; ++n) {
            float4 v;
            v.x = accO[n][0]; v.y = accO[n][1]; v.z = accO[n][2]; v.w = accO[n][3];
            *reinterpret_cast<float4*>(
                out + ((i_n * B_ + b) * C_ + (o0 + n)) * HW + pbase + px) = v;
        }
    }
}

extern "C" void kernel_launch(void* const* d_in, const int* in_sizes, int n_in,
                              void* d_out, int out_size) {
    const float* nodes = (const float*)d_in[0];
    const float* W     = (const float*)d_in[1];
    const float* bvec  = (const float*)d_in[2];
    float* out         = (float*)d_out;

    float *buf0 = nullptr, *buf1 = nullptr;
    cudaGetSymbolAddress((void**)&buf0, g_buf0);
    cudaGetSymbolAddress((void**)&buf1, g_buf1);

    cudaFuncSetAttribute(step_kernel,
                         cudaFuncAttributeMaxDynamicSharedMemorySize, SMEM_BYTES);

    const dim3 grid(B_ * NT);   // 288 blocks
    const dim3 block(256);

    step_kernel<<<grid, block, SMEM_BYTES>>>(nodes, W, bvec, buf0);
    step_kernel<<<grid, block, SMEM_BYTES>>>(buf0,  W, bvec, buf1);
    step_kernel<<<grid, block, SMEM_BYTES>>>(buf1,  W, bvec, out);
}